// round 2
// baseline (speedup 1.0000x reference)
#include <cuda_runtime.h>

#define N_NODES 50000
#define N_EDGES 800000
#define IN_DIM 128
#define OUT_DIM 64

// ---------------- scratch (no allocations allowed) ----------------
__device__ float    g_Wh[N_NODES * OUT_DIM];   // projected features
__device__ float    g_adst[N_NODES];           // Wh . A_w[:64]
__device__ float    g_asrc[N_NODES];           // Wh . A_w[64:]
__device__ float    g_e[N_EDGES];              // edge logit, then exp(e - m)
__device__ unsigned g_mbits[N_NODES];          // segment max as sortable uint
__device__ float    g_den[N_NODES];            // softmax denominator

// float <-> order-preserving uint (for atomicMax on floats incl. negatives)
__device__ __forceinline__ unsigned f2sort(float f) {
    unsigned b = __float_as_uint(f);
    return (b & 0x80000000u) ? ~b : (b | 0x80000000u);
}
__device__ __forceinline__ float sort2f(unsigned u) {
    return __uint_as_float((u & 0x80000000u) ? (u & 0x7fffffffu) : ~u);
}

// ---------------- kernel 0: init ----------------
__global__ void k_init(float4* __restrict__ out4) {
    int i = blockIdx.x * blockDim.x + threadIdx.x;
    int stride = gridDim.x * blockDim.x;
    const float4 z = make_float4(0.f, 0.f, 0.f, 0.f);
    for (int j = i; j < N_NODES * (OUT_DIM / 4); j += stride) out4[j] = z;
    for (int j = i; j < N_NODES; j += stride) {
        g_den[j] = 0.f;
        g_mbits[j] = 0x007FFFFFu;  // f2sort(-inf)
    }
}

// ---------------- kernel 1: Wh = h@W + b, plus a_dst/a_src partial dots ----
// Block: 256 threads computes 64 rows x 64 cols. K chunked by 64.
__global__ __launch_bounds__(256) void k_gemm(
    const float* __restrict__ h, const float* __restrict__ Ww,
    const float* __restrict__ Wb, const float* __restrict__ Aw)
{
    __shared__ float sh_h[64][65];   // padded
    __shared__ float sW[64][64];     // [k][col]

    const int tid = threadIdx.x;
    const int cg  = tid & 7;         // col group: cols cg*8 .. cg*8+7
    const int r0  = tid >> 3;        // 0..31 ; handles rows r0 and r0+32
    const int row0 = blockIdx.x * 64;

    float acc[2][8];
#pragma unroll
    for (int r = 0; r < 2; r++)
#pragma unroll
        for (int j = 0; j < 8; j++) acc[r][j] = 0.f;

    for (int kc = 0; kc < IN_DIM; kc += 64) {
        __syncthreads();
        // load h tile: 64 rows x 64 cols = 1024 float4
#pragma unroll
        for (int p = 0; p < 4; p++) {
            int idx = p * 256 + tid;          // float4 index
            int row = idx >> 4;               // 16 float4 per row
            int c4  = idx & 15;
            int gr  = row0 + row;
            float4 v = make_float4(0.f, 0.f, 0.f, 0.f);
            if (gr < N_NODES)
                v = *reinterpret_cast<const float4*>(&h[gr * IN_DIM + kc + c4 * 4]);
            sh_h[row][c4 * 4 + 0] = v.x;
            sh_h[row][c4 * 4 + 1] = v.y;
            sh_h[row][c4 * 4 + 2] = v.z;
            sh_h[row][c4 * 4 + 3] = v.w;
        }
        // load W tile: 64 k x 64 cols
#pragma unroll
        for (int p = 0; p < 4; p++) {
            int idx = p * 256 + tid;
            int k  = idx >> 4;
            int c4 = idx & 15;
            float4 v = *reinterpret_cast<const float4*>(&Ww[(kc + k) * OUT_DIM + c4 * 4]);
            *reinterpret_cast<float4*>(&sW[k][c4 * 4]) = v;
        }
        __syncthreads();

#pragma unroll
        for (int k = 0; k < 64; k++) {
            float a0 = sh_h[r0][k];
            float a1 = sh_h[r0 + 32][k];
            float4 w0 = *reinterpret_cast<const float4*>(&sW[k][cg * 8]);
            float4 w1 = *reinterpret_cast<const float4*>(&sW[k][cg * 8 + 4]);
            acc[0][0] += a0 * w0.x; acc[0][1] += a0 * w0.y;
            acc[0][2] += a0 * w0.z; acc[0][3] += a0 * w0.w;
            acc[0][4] += a0 * w1.x; acc[0][5] += a0 * w1.y;
            acc[0][6] += a0 * w1.z; acc[0][7] += a0 * w1.w;
            acc[1][0] += a1 * w0.x; acc[1][1] += a1 * w0.y;
            acc[1][2] += a1 * w0.z; acc[1][3] += a1 * w0.w;
            acc[1][4] += a1 * w1.x; acc[1][5] += a1 * w1.y;
            acc[1][6] += a1 * w1.z; acc[1][7] += a1 * w1.w;
        }
    }

    // bias
#pragma unroll
    for (int j = 0; j < 8; j++) {
        float b = Wb[cg * 8 + j];
        acc[0][j] += b;
        acc[1][j] += b;
    }

    // attention partials: pd = sum_j acc[j]*Aw[col], ps = sum_j acc[j]*Aw[64+col]
    float pd[2] = {0.f, 0.f}, ps[2] = {0.f, 0.f};
#pragma unroll
    for (int j = 0; j < 8; j++) {
        float a1v = Aw[cg * 8 + j];
        float a2v = Aw[OUT_DIM + cg * 8 + j];
        pd[0] += acc[0][j] * a1v; ps[0] += acc[0][j] * a2v;
        pd[1] += acc[1][j] * a1v; ps[1] += acc[1][j] * a2v;
    }
    // reduce across the 8 threads sharing a row (cg = lane%8 groups)
#pragma unroll
    for (int off = 1; off < 8; off <<= 1) {
        pd[0] += __shfl_xor_sync(0xffffffffu, pd[0], off);
        ps[0] += __shfl_xor_sync(0xffffffffu, ps[0], off);
        pd[1] += __shfl_xor_sync(0xffffffffu, pd[1], off);
        ps[1] += __shfl_xor_sync(0xffffffffu, ps[1], off);
    }

    // write Wh + partials
#pragma unroll
    for (int r = 0; r < 2; r++) {
        int gr = row0 + r0 + r * 32;
        if (gr < N_NODES) {
            float4 o0 = make_float4(acc[r][0], acc[r][1], acc[r][2], acc[r][3]);
            float4 o1 = make_float4(acc[r][4], acc[r][5], acc[r][6], acc[r][7]);
            *reinterpret_cast<float4*>(&g_Wh[gr * OUT_DIM + cg * 8])     = o0;
            *reinterpret_cast<float4*>(&g_Wh[gr * OUT_DIM + cg * 8 + 4]) = o1;
            if (cg == 0) {
                g_adst[gr] = pd[r];
                g_asrc[gr] = ps[r];
            }
        }
    }
}

// ---------------- kernel 2: edge logits + segment max ----------------
__global__ void k_edge_logit(const int* __restrict__ src,
                             const int* __restrict__ dst,
                             const float* __restrict__ Ab) {
    int i = blockIdx.x * blockDim.x + threadIdx.x;
    int stride = gridDim.x * blockDim.x;
    float ab = Ab[0];
    for (int e = i; e < N_EDGES; e += stride) {
        int s = src[e], d = dst[e];
        float x = g_adst[d] + g_asrc[s] + ab;
        float v = x > 0.f ? x : 0.2f * x;   // leaky relu
        g_e[e] = v;
        atomicMax(&g_mbits[d], f2sort(v));
    }
}

// ---------------- kernel 3: exp + denominator ----------------
__global__ void k_edge_exp(const int* __restrict__ dst) {
    int i = blockIdx.x * blockDim.x + threadIdx.x;
    int stride = gridDim.x * blockDim.x;
    for (int e = i; e < N_EDGES; e += stride) {
        int d = dst[e];
        float m = sort2f(g_mbits[d]);
        float ex = __expf(g_e[e] - m);
        g_e[e] = ex;                         // store exp in place
        atomicAdd(&g_den[d], ex);
    }
}

// ---------------- kernel 4: weighted scatter-sum ----------------
// 16 threads per edge, one float4 per thread (64 floats per edge).
__global__ __launch_bounds__(256) void k_scatter(
    const int* __restrict__ src, const int* __restrict__ dst,
    float4* __restrict__ out4) {
    int t = blockIdx.x * 256 + threadIdx.x;
    int e  = t >> 4;
    int ln = t & 15;
    if (e >= N_EDGES) return;
    int s = src[e], d = dst[e];
    float alpha = g_e[e] / g_den[d];
    const float4* Wh4 = reinterpret_cast<const float4*>(g_Wh);
    float4 v = Wh4[s * 16 + ln];
    v.x *= alpha; v.y *= alpha; v.z *= alpha; v.w *= alpha;
    atomicAdd(&out4[d * 16 + ln], v);
}

// ---------------- launch ----------------
extern "C" void kernel_launch(void* const* d_in, const int* in_sizes, int n_in,
                              void* d_out, int out_size) {
    const float* h   = (const float*)d_in[0];
    const float* Ww  = (const float*)d_in[1];
    const float* Wb  = (const float*)d_in[2];
    const float* Aw  = (const float*)d_in[3];
    const float* Ab  = (const float*)d_in[4];
    const int*   src = (const int*)d_in[5];
    const int*   dst = (const int*)d_in[6];
    float4* out4 = (float4*)d_out;

    k_init<<<2048, 256>>>(out4);
    k_gemm<<<(N_NODES + 63) / 64, 256>>>(h, Ww, Wb, Aw);
    k_edge_logit<<<(N_EDGES + 255) / 256, 256>>>(src, dst, Ab);
    k_edge_exp<<<(N_EDGES + 255) / 256, 256>>>(dst);
    k_scatter<<<(N_EDGES * 16 + 255) / 256, 256>>>(src, dst, out4);
}